// round 2
// baseline (speedup 1.0000x reference)
#include <cuda_runtime.h>

#define BB 2
#define HH 64
#define WW 64
#define CC 128
#define NHEAD 4
#define HD 32
#define KWIN 7
#define MROWS (BB*HH*WW)          /* 8192 */
#define SCALE 0.17677669529663687f /* 32^-0.5 */

// Scratch (allocation-free rule: device globals)
__device__ float g_q[MROWS*CC];
__device__ float g_k[MROWS*CC];
__device__ float g_v[MROWS*CC];
__device__ float g_att[MROWS*CC];

// ---------------------------------------------------------------------------
// Tiled fp32 GEMM: A[M,128] @ W[128,NTOT] + bias
// MODE 0: split epilogue -> g_q (scaled), g_k, g_v   (NTOT=384), A = x
// MODE 1: out[row*NTOT+col] = val                    (NTOT=128), A = g_att
// Tile 64x64, 256 threads, 4x4 per thread, K-chunk 16.
// ---------------------------------------------------------------------------
template<int NTOT, int MODE>
__global__ __launch_bounds__(256)
void gemm_k(const float* __restrict__ A,
            const float* __restrict__ W,
            const float* __restrict__ bias,
            float* __restrict__ out) {
    __shared__ float  As[16][68];   // transposed A tile [k][m], padded
    __shared__ float4 Bs[16][16];   // B tile [k][n/4]

    const float* Ap = (MODE == 1) ? (const float*)g_att : A;

    const int tid = threadIdx.x;
    const int tx  = tid & 15;       // col group
    const int ty  = tid >> 4;       // row group
    const int rowbase = blockIdx.x * 64;
    const int colbase = blockIdx.y * 64;

    const int arow  = tid >> 2;         // 0..63
    const int acol4 = (tid & 3) * 4;    // 0,4,8,12
    const int brow  = tid >> 4;         // 0..15
    const int bcol  = tid & 15;         // 0..15

    float acc[4][4];
    #pragma unroll
    for (int i = 0; i < 4; ++i)
        #pragma unroll
        for (int j = 0; j < 4; ++j) acc[i][j] = 0.f;

    for (int k0 = 0; k0 < 128; k0 += 16) {
        float4 av = *(const float4*)&Ap[(rowbase + arow) * 128 + k0 + acol4];
        As[acol4 + 0][arow] = av.x;
        As[acol4 + 1][arow] = av.y;
        As[acol4 + 2][arow] = av.z;
        As[acol4 + 3][arow] = av.w;
        Bs[brow][bcol] = *(const float4*)&W[(k0 + brow) * NTOT + colbase + bcol * 4];
        __syncthreads();

        #pragma unroll
        for (int kk = 0; kk < 16; ++kk) {
            float4 a = *(const float4*)&As[kk][ty * 4];
            float4 b = Bs[kk][tx];
            acc[0][0] += a.x * b.x; acc[0][1] += a.x * b.y; acc[0][2] += a.x * b.z; acc[0][3] += a.x * b.w;
            acc[1][0] += a.y * b.x; acc[1][1] += a.y * b.y; acc[1][2] += a.y * b.z; acc[1][3] += a.y * b.w;
            acc[2][0] += a.z * b.x; acc[2][1] += a.z * b.y; acc[2][2] += a.z * b.z; acc[2][3] += a.z * b.w;
            acc[3][0] += a.w * b.x; acc[3][1] += a.w * b.y; acc[3][2] += a.w * b.z; acc[3][3] += a.w * b.w;
        }
        __syncthreads();
    }

    #pragma unroll
    for (int i = 0; i < 4; ++i) {
        const int row = rowbase + ty * 4 + i;
        #pragma unroll
        for (int j = 0; j < 4; ++j) {
            const int col = colbase + tx * 4 + j;
            float v = acc[i][j] + bias[col];
            if (MODE == 0) {
                const int comp  = col >> 7;     // 0=q 1=k 2=v
                const int inner = col & 127;    // nh*32 + d
                if (comp == 0)      g_q[row * CC + inner] = v * SCALE;
                else if (comp == 1) g_k[row * CC + inner] = v;
                else                g_v[row * CC + inner] = v;
            } else {
                out[row * NTOT + col] = v;
            }
        }
    }
}

// ---------------------------------------------------------------------------
// Neighborhood attention: one block per pixel, 4 warps = 4 heads, lane = dim.
// Online softmax fused with V accumulation (single pass over 49 neighbors).
// Writes directly to the g_att device global (no symbol-address plumbing).
// ---------------------------------------------------------------------------
__global__ __launch_bounds__(128)
void natten_kernel(const float* __restrict__ rpb) {
    const int pix  = blockIdx.x;            // b*H*W + h*W + w
    const int tid  = threadIdx.x;
    const int nh   = tid >> 5;

    const int w = pix & 63;
    const int h = (pix >> 6) & 63;
    const int b = pix >> 12;

    int hs = h - 3; hs = hs < 0 ? 0 : (hs > 57 ? 57 : hs);
    int ws = w - 3; ws = ws < 0 ? 0 : (ws > 57 ? 57 : ws);

    const float qd = g_q[pix * CC + tid];   // already *SCALE
    const float* rp = rpb + nh * 169;       // 13*13 table for this head

    float m = -1e30f, l = 0.f, acc = 0.f;
    const int brow = b << 12;               // b*4096

    #pragma unroll
    for (int p = 0; p < KWIN; ++p) {
        const int kh = hs + p;
        const int bih = (kh - h + 6) * 13;
        const int rowb = (brow + (kh << 6)) * CC;
        #pragma unroll
        for (int q = 0; q < KWIN; ++q) {
            const int kw  = ws + q;
            const int off = rowb + kw * CC + tid;   // tid = nh*32+lane
            float s = qd * g_k[off];
            s += __shfl_xor_sync(0xffffffffu, s, 16);
            s += __shfl_xor_sync(0xffffffffu, s, 8);
            s += __shfl_xor_sync(0xffffffffu, s, 4);
            s += __shfl_xor_sync(0xffffffffu, s, 2);
            s += __shfl_xor_sync(0xffffffffu, s, 1);
            s += rp[bih + (kw - w + 6)];

            const float mn = fmaxf(m, s);
            const float c  = __expf(m - mn);
            const float e  = __expf(s - mn);
            l   = l * c + e;
            acc = acc * c + e * g_v[off];
            m = mn;
        }
    }
    g_att[pix * CC + tid] = acc / l;
}

extern "C" void kernel_launch(void* const* d_in, const int* in_sizes, int n_in,
                              void* d_out, int out_size) {
    (void)in_sizes; (void)n_in; (void)out_size;
    const float* x      = (const float*)d_in[0];
    const float* w_qkv  = (const float*)d_in[1];
    const float* b_qkv  = (const float*)d_in[2];
    const float* rpb    = (const float*)d_in[3];
    const float* w_proj = (const float*)d_in[4];
    const float* b_proj = (const float*)d_in[5];
    float* out = (float*)d_out;

    dim3 g1(MROWS / 64, 384 / 64);
    gemm_k<384, 0><<<g1, 256>>>(x, w_qkv, b_qkv, nullptr);

    natten_kernel<<<MROWS, 128>>>(rpb);

    dim3 g2(MROWS / 64, 128 / 64);
    gemm_k<128, 1><<<g2, 256>>>(nullptr, w_proj, b_proj, out);
}